// round 11
// baseline (speedup 1.0000x reference)
#include <cuda_runtime.h>
#include <cuda_bf16.h>
#include <math.h>

#define N_NODES   100000
#define N_EDGES   3200000
#define N_GRAPHS  64
#define FC_OUT    160000
#define NB_SCAN   98          // ceil(100000/1024)
#define FULLMASK  0xffffffffu

typedef __nv_bfloat16  bf16;
typedef __nv_bfloat162 bf162;

// ---------------- scratch (static __device__, no allocations) ----------------
__device__ int   g_deg[N_NODES];
__device__ float g_dinv[N_NODES];
__device__ int   g_rowptr[N_NODES + 1];
__device__ int   g_cursor[N_NODES];
__device__ int   g_blocksums[NB_SCAN + 1];
__device__ int   g_csr_src[N_EDGES];
__device__ bf16  g_t1[(size_t)N_NODES * 32];   // dinv-scaled x@W1
__device__ bf16  g_h1[(size_t)N_NODES * 32];   // dinv-scaled relu layer1
__device__ bf16  g_h2[(size_t)N_NODES * 64];   // dinv-scaled relu layer2
__device__ float g_W1f[64 * 32];
__device__ float g_b1f[32];
__device__ float g_W2f[32 * 64];
__device__ float g_b2f[64];
__device__ float g_W3f[64 * 128];
__device__ float g_b3f[128];
__device__ float g_pool[N_GRAPHS * 128];
__device__ int   g_cnt[N_GRAPHS];
__device__ float g_z[N_GRAPHS * 64];

// ---------------- init + weight packing (fused) ----------------
__global__ void zeropack_kernel(const float* __restrict__ W1m, const float* __restrict__ b1m,
                                const float* __restrict__ W2m, const float* __restrict__ b2m,
                                const float* __restrict__ W3m, const float* __restrict__ b3m,
                                const float* __restrict__ W1l, const float* __restrict__ b1l,
                                const float* __restrict__ W2l, const float* __restrict__ b2l,
                                const float* __restrict__ W3l, const float* __restrict__ b3l) {
    int i = blockIdx.x * 256 + threadIdx.x;
    if (i < N_NODES) g_deg[i] = 0;
    if (i < N_GRAPHS * 128) g_pool[i] = 0.f;
    if (i < N_GRAPHS) g_cnt[i] = 0;

    if (i < 64 * 32) {
        int j = i / 32, o = i % 32;
        g_W1f[i] = (o < 16) ? W1m[j * 16 + o] : W1l[j * 16 + (o - 16)];
    }
    if (i < 32) g_b1f[i] = (i < 16) ? b1m[i] : b1l[i - 16];
    if (i < 32 * 64) {
        int j = i / 64, o = i % 64;
        float v = 0.f;
        if (o < 32) { if (j < 16)  v = W2m[j * 32 + o]; }
        else        { if (j >= 16) v = W2l[(j - 16) * 32 + (o - 32)]; }
        g_W2f[i] = v;
    }
    if (i < 64) g_b2f[i] = (i < 32) ? b2m[i] : b2l[i - 32];
    if (i < 64 * 128) {
        int j = i / 128, o = i % 128;
        float v = 0.f;
        if (o < 64) { if (j < 32)  v = W3m[j * 64 + o]; }
        else        { if (j >= 32) v = W3l[(j - 32) * 64 + (o - 64)]; }
        g_W3f[i] = v;
    }
    if (i < 128) g_b3f[i] = (i < 64) ? b3m[i] : b3l[i - 64];
}

// ---------------- degree hist + per-graph node count (fused) ----------------
__global__ void hist_count_kernel(const int* __restrict__ dst, const int* __restrict__ batch) {
    int e = blockIdx.x * 256 + threadIdx.x;
    if (e < N_EDGES) atomicAdd(&g_deg[dst[e]], 1);
    if (e < N_NODES) atomicAdd(&g_cnt[batch[e]], 1);
}

// ---------------- scan (block-local) + dinv (fused) ----------------
__global__ void scan1_kernel() {
    __shared__ int sh[1024];
    int i = blockIdx.x * 1024 + threadIdx.x;
    int v = (i < N_NODES) ? g_deg[i] : 0;
    if (i < N_NODES) g_dinv[i] = rsqrtf((float)v + 1.0f);
    sh[threadIdx.x] = v;
    __syncthreads();
    for (int off = 1; off < 1024; off <<= 1) {
        int t = (threadIdx.x >= off) ? sh[threadIdx.x - off] : 0;
        __syncthreads();
        sh[threadIdx.x] += t;
        __syncthreads();
    }
    if (i < N_NODES) g_rowptr[i] = sh[threadIdx.x] - v;
    if (threadIdx.x == 1023) g_blocksums[blockIdx.x] = sh[1023];
}

__global__ void scan2_kernel() {
    __shared__ int sh[128];
    int t = threadIdx.x;
    int v = (t < NB_SCAN) ? g_blocksums[t] : 0;
    sh[t] = v;
    __syncthreads();
    for (int off = 1; off < 128; off <<= 1) {
        int u = (t >= off) ? sh[t - off] : 0;
        __syncthreads();
        sh[t] += u;
        __syncthreads();
    }
    if (t < NB_SCAN) g_blocksums[t] = sh[t] - v;   // exclusive
}

__global__ void scan3_kernel() {
    int i = blockIdx.x * 1024 + threadIdx.x;
    if (i < N_NODES) {
        int r = g_rowptr[i] + g_blocksums[blockIdx.x];
        g_rowptr[i] = r;
        g_cursor[i] = r;
    }
    if (i == 0) g_rowptr[N_NODES] = N_EDGES;
}

__global__ void fill_kernel(const int* __restrict__ src, const int* __restrict__ dst) {
    int e = blockIdx.x * 256 + threadIdx.x;
    if (e < N_EDGES) {
        int p = atomicAdd(&g_cursor[dst[e]], 1);
        g_csr_src[p] = src[e];
    }
}

// ---------------- pair-edge gather over 32-feature bf16 table ----------------
__device__ __forceinline__ float2 gather_pair32(const bf16* __restrict__ t, int i, int lane) {
    const int half = lane >> 4;
    const int l16 = lane & 15;
    int beg = __ldg(&g_rowptr[i]), end = __ldg(&g_rowptr[i + 1]);
    float ax = 0.f, ay = 0.f;
    int e = beg;
    while (e < end) {
        int cnt = min(end - e, 32);
        int idx = 0;
        if (lane < cnt) idx = __ldg(&g_csr_src[e + lane]);
        int pairs = cnt >> 1;
#pragma unroll 4
        for (int k = 0; k < pairs; k++) {
            int s = __shfl_sync(FULLMASK, idx, 2 * k + half);
            float2 f = __bfloat1622float2(__ldg((const bf162*)(t + (size_t)s * 32) + l16));
            ax += f.x; ay += f.y;
        }
        if (cnt & 1) {
            int s = __shfl_sync(FULLMASK, idx, cnt - 1);
            if (half == 0) {
                float2 f = __bfloat1622float2(__ldg((const bf162*)(t + (size_t)s * 32) + l16));
                ax += f.x; ay += f.y;
            }
        }
        e += cnt;
    }
    ax += __shfl_xor_sync(FULLMASK, ax, 16);
    ay += __shfl_xor_sync(FULLMASK, ay, 16);
    float2 fs = __bfloat1622float2(__ldg((const bf162*)(t + (size_t)i * 32) + l16));
    return make_float2(ax + fs.x, ay + fs.y);
}

// ---------------- pair-edge gather over 64-feature bf16 table ----------------
__device__ __forceinline__ float4 gather_pair64(const bf16* __restrict__ t, int i, int lane) {
    const int half = lane >> 4;
    const int l16 = lane & 15;
    int beg = __ldg(&g_rowptr[i]), end = __ldg(&g_rowptr[i + 1]);
    float a0 = 0.f, a1 = 0.f, a2 = 0.f, a3 = 0.f;
    int e = beg;
    while (e < end) {
        int cnt = min(end - e, 32);
        int idx = 0;
        if (lane < cnt) idx = __ldg(&g_csr_src[e + lane]);
        int pairs = cnt >> 1;
#pragma unroll 4
        for (int k = 0; k < pairs; k++) {
            int s = __shfl_sync(FULLMASK, idx, 2 * k + half);
            uint2 u = __ldg((const uint2*)(t + (size_t)s * 64) + l16);
            float2 f0 = __bfloat1622float2(*(const bf162*)&u.x);
            float2 f1 = __bfloat1622float2(*(const bf162*)&u.y);
            a0 += f0.x; a1 += f0.y; a2 += f1.x; a3 += f1.y;
        }
        if (cnt & 1) {
            int s = __shfl_sync(FULLMASK, idx, cnt - 1);
            if (half == 0) {
                uint2 u = __ldg((const uint2*)(t + (size_t)s * 64) + l16);
                float2 f0 = __bfloat1622float2(*(const bf162*)&u.x);
                float2 f1 = __bfloat1622float2(*(const bf162*)&u.y);
                a0 += f0.x; a1 += f0.y; a2 += f1.x; a3 += f1.y;
            }
        }
        e += cnt;
    }
    a0 += __shfl_xor_sync(FULLMASK, a0, 16);
    a1 += __shfl_xor_sync(FULLMASK, a1, 16);
    a2 += __shfl_xor_sync(FULLMASK, a2, 16);
    a3 += __shfl_xor_sync(FULLMASK, a3, 16);
    uint2 us = __ldg((const uint2*)(t + (size_t)i * 64) + l16);
    float2 s0 = __bfloat1622float2(*(const bf162*)&us.x);
    float2 s1 = __bfloat1622float2(*(const bf162*)&us.y);
    return make_float4(a0 + s0.x, a1 + s0.y, a2 + s1.x, a3 + s1.y);
}

// ---------------- dense1: t1' = dinv[i] * (x[i] @ W1f), bf16 out ----------------
__global__ void dense1_kernel(const float* __restrict__ x) {
    __shared__ float Ws[64 * 32];
    int tid = threadIdx.y * 32 + threadIdx.x;
    for (int idx = tid; idx < 64 * 32; idx += 256) Ws[idx] = g_W1f[idx];
    __syncthreads();

    int i = blockIdx.x * 8 + threadIdx.y;
    int o = threadIdx.x;
    const float2* xr = (const float2*)(x + (size_t)i * 64);
    float2 xv = __ldg(&xr[o]);
    float acc = 0.f;
#pragma unroll
    for (int jj = 0; jj < 32; jj++) {
        float vx = __shfl_sync(FULLMASK, xv.x, jj);
        float vy = __shfl_sync(FULLMASK, xv.y, jj);
        acc = fmaf(vx, Ws[(2 * jj) * 32 + o], acc);
        acc = fmaf(vy, Ws[(2 * jj + 1) * 32 + o], acc);
    }
    float di = __ldg(&g_dinv[i]);
    g_t1[(size_t)i * 32 + o] = __float2bfloat16(di * acc);
}

// ---------------- G1: h1' = dinv * relu(dinv*(sum t1') + b1) ----------------
__global__ void gather1_kernel() {
    int i = blockIdx.x * 8 + threadIdx.y;
    int lane = threadIdx.x;
    int l16 = lane & 15;
    float2 g = gather_pair32(g_t1, i, lane);
    float di = __ldg(&g_dinv[i]);
    float2 b = __ldg((const float2*)g_b1f + l16);
    float h0 = fmaxf(fmaf(di, g.x, b.x), 0.f) * di;
    float h1 = fmaxf(fmaf(di, g.y, b.y), 0.f) * di;
    if (lane < 16)
        ((bf162*)(g_h1 + (size_t)i * 32))[l16] = __float22bfloat162_rn(make_float2(h0, h1));
}

// ---------------- G2+dense2: gather h1' -> g2, h2 = relu(g2@W2+b2), store h2' ----------
__global__ void gather2_dense_kernel() {
    __shared__ float Ws[32 * 64];
    int tid = threadIdx.y * 32 + threadIdx.x;
    for (int idx = tid; idx < 32 * 64; idx += 256) Ws[idx] = g_W2f[idx];
    __syncthreads();

    int i = blockIdx.x * 8 + threadIdx.y;
    int l = threadIdx.x;
    float2 gp = gather_pair32(g_h1, i, l);   // lane: g2[2*(l&15)], g2[2*(l&15)+1]
    float di = __ldg(&g_dinv[i]);
    float g2x = di * gp.x, g2y = di * gp.y;

    // block-diagonal dense: out[l] from j 0..15 (mu), out[l+32] from j 16..31 (logvar)
    float accA = __ldg(&g_b2f[l]);
    float accB = __ldg(&g_b2f[l + 32]);
#pragma unroll
    for (int jj = 0; jj < 8; jj++) {
        float vx = __shfl_sync(FULLMASK, g2x, jj);        // feature 2jj
        float vy = __shfl_sync(FULLMASK, g2y, jj);        // feature 2jj+1
        accA = fmaf(vx, Ws[(2 * jj) * 64 + l], accA);
        accA = fmaf(vy, Ws[(2 * jj + 1) * 64 + l], accA);
    }
#pragma unroll
    for (int jj = 8; jj < 16; jj++) {
        float vx = __shfl_sync(FULLMASK, g2x, jj);        // feature 2jj (16..31)
        float vy = __shfl_sync(FULLMASK, g2y, jj);
        accB = fmaf(vx, Ws[(2 * jj) * 64 + 32 + l], accB);
        accB = fmaf(vy, Ws[(2 * jj + 1) * 64 + 32 + l], accB);
    }
    float h2a = fmaxf(accA, 0.f), h2b = fmaxf(accB, 0.f);
    g_h2[(size_t)i * 64 + l]      = __float2bfloat16(di * h2a);
    g_h2[(size_t)i * 64 + l + 32] = __float2bfloat16(di * h2b);
}

// ---------------- G3+dense3+pool ----------------
__global__ void gather3_dense_pool_kernel(const int* __restrict__ batch) {
    __shared__ float Ws[64 * 128];     // 32 KB
    __shared__ float pacc[128];
    int tid = threadIdx.y * 32 + threadIdx.x;
    for (int idx = tid; idx < 64 * 128; idx += 256) Ws[idx] = g_W3f[idx];
    if (tid < 128) pacc[tid] = 0.f;
    __syncthreads();

    int i = blockIdx.x * 8 + threadIdx.y;
    int l = threadIdx.x;
    int g0 = __ldg(&batch[blockIdx.x * 8]);

    float4 gp = gather_pair64(g_h2, i, l);   // lane: g3[4*(l&15) .. +3]
    float di = __ldg(&g_dinv[i]);
    float v0 = di * gp.x, v1 = di * gp.y, v2 = di * gp.z, v3 = di * gp.w;

    float a0 = __ldg(&g_b3f[2 * l]);
    float a1 = __ldg(&g_b3f[2 * l + 1]);
    float a2 = __ldg(&g_b3f[64 + 2 * l]);
    float a3 = __ldg(&g_b3f[65 + 2 * l]);
#pragma unroll
    for (int jj = 0; jj < 8; jj++) {   // features 4jj..4jj+3 (0..31)
        float w0 = __shfl_sync(FULLMASK, v0, jj);
        float w1 = __shfl_sync(FULLMASK, v1, jj);
        float w2 = __shfl_sync(FULLMASK, v2, jj);
        float w3 = __shfl_sync(FULLMASK, v3, jj);
        a0 = fmaf(w0, Ws[(4 * jj) * 128 + 2 * l], a0);
        a0 = fmaf(w1, Ws[(4 * jj + 1) * 128 + 2 * l], a0);
        a0 = fmaf(w2, Ws[(4 * jj + 2) * 128 + 2 * l], a0);
        a0 = fmaf(w3, Ws[(4 * jj + 3) * 128 + 2 * l], a0);
        a1 = fmaf(w0, Ws[(4 * jj) * 128 + 2 * l + 1], a1);
        a1 = fmaf(w1, Ws[(4 * jj + 1) * 128 + 2 * l + 1], a1);
        a1 = fmaf(w2, Ws[(4 * jj + 2) * 128 + 2 * l + 1], a1);
        a1 = fmaf(w3, Ws[(4 * jj + 3) * 128 + 2 * l + 1], a1);
    }
#pragma unroll
    for (int jj = 8; jj < 16; jj++) {  // features 4jj..4jj+3 (32..63)
        float w0 = __shfl_sync(FULLMASK, v0, jj);
        float w1 = __shfl_sync(FULLMASK, v1, jj);
        float w2 = __shfl_sync(FULLMASK, v2, jj);
        float w3 = __shfl_sync(FULLMASK, v3, jj);
        a2 = fmaf(w0, Ws[(4 * jj) * 128 + 64 + 2 * l], a2);
        a2 = fmaf(w1, Ws[(4 * jj + 1) * 128 + 64 + 2 * l], a2);
        a2 = fmaf(w2, Ws[(4 * jj + 2) * 128 + 64 + 2 * l], a2);
        a2 = fmaf(w3, Ws[(4 * jj + 3) * 128 + 64 + 2 * l], a2);
        a3 = fmaf(w0, Ws[(4 * jj) * 128 + 65 + 2 * l], a3);
        a3 = fmaf(w1, Ws[(4 * jj + 1) * 128 + 65 + 2 * l], a3);
        a3 = fmaf(w2, Ws[(4 * jj + 2) * 128 + 65 + 2 * l], a3);
        a3 = fmaf(w3, Ws[(4 * jj + 3) * 128 + 65 + 2 * l], a3);
    }
    a0 = fmaxf(a0, 0.f); a1 = fmaxf(a1, 0.f);
    a2 = fmaxf(a2, 0.f); a3 = fmaxf(a3, 0.f);

    int g = __ldg(&batch[i]);
    if (g == g0) {
        atomicAdd(&pacc[2 * l], a0);
        atomicAdd(&pacc[2 * l + 1], a1);
        atomicAdd(&pacc[64 + 2 * l], a2);
        atomicAdd(&pacc[65 + 2 * l], a3);
    } else {   // rare graph-boundary nodes
        atomicAdd(&g_pool[g * 128 + 2 * l], a0);
        atomicAdd(&g_pool[g * 128 + 2 * l + 1], a1);
        atomicAdd(&g_pool[g * 128 + 64 + 2 * l], a2);
        atomicAdd(&g_pool[g * 128 + 65 + 2 * l], a3);
    }
    __syncthreads();
    if (tid < 128) atomicAdd(&g_pool[g0 * 128 + tid], pacc[tid]);
}

// ---------------- latent: mu, logvar, z ----------------
__global__ void latent_kernel(const float* __restrict__ eps, float* __restrict__ d_out) {
    int idx = blockIdx.x * 256 + threadIdx.x;
    if (idx >= N_GRAPHS * 64) return;
    int g = idx >> 6, f = idx & 63;
    float c = fmaxf((float)g_cnt[g], 1.0f);
    float mu = g_pool[g * 128 + f] / c;
    float lv = g_pool[g * 128 + 64 + f] / c;
    d_out[(size_t)N_GRAPHS * FC_OUT + idx] = mu;
    d_out[(size_t)N_GRAPHS * FC_OUT + N_GRAPHS * 64 + idx] = lv;
    g_z[idx] = mu + eps[idx] * expf(0.5f * lv);
}

// ---------------- FC decode: sigmoid(z @ Wfc + bfc) ----------------
__global__ void fc_kernel(const float* __restrict__ Wfc,
                          const float* __restrict__ bfc,
                          float* __restrict__ out) {
    __shared__ float zT[64 * 65];
    int tid = threadIdx.y * 64 + threadIdx.x;
    for (int i = tid; i < 64 * 64; i += 256) {
        int g = i & 63, j = i >> 6;
        zT[j * 65 + g] = g_z[g * 64 + j];
    }
    __syncthreads();

    int kq = blockIdx.x * 64 + threadIdx.x;
    int g0 = threadIdx.y * 16;
    const float4* W4 = (const float4*)Wfc;
    float4 bv = ((const float4*)bfc)[kq];

    float4 acc[16];
#pragma unroll
    for (int gi = 0; gi < 16; gi++) acc[gi] = bv;

#pragma unroll 4
    for (int j = 0; j < 64; j++) {
        float4 w = W4[(size_t)j * (FC_OUT / 4) + kq];
#pragma unroll
        for (int gi = 0; gi < 16; gi++) {
            float zv = zT[j * 65 + g0 + gi];
            acc[gi].x = fmaf(zv, w.x, acc[gi].x);
            acc[gi].y = fmaf(zv, w.y, acc[gi].y);
            acc[gi].z = fmaf(zv, w.z, acc[gi].z);
            acc[gi].w = fmaf(zv, w.w, acc[gi].w);
        }
    }

#pragma unroll
    for (int gi = 0; gi < 16; gi++) {
        int g = g0 + gi;
        float4 v = acc[gi];
        v.x = 1.f / (1.f + __expf(-v.x));
        v.y = 1.f / (1.f + __expf(-v.y));
        v.z = 1.f / (1.f + __expf(-v.z));
        v.w = 1.f / (1.f + __expf(-v.w));
        ((float4*)out)[(size_t)g * (FC_OUT / 4) + kq] = v;
    }
}

// ---------------- launch ----------------
extern "C" void kernel_launch(void* const* d_in, const int* in_sizes, int n_in,
                              void* d_out, int out_size) {
    const float* x     = (const float*)d_in[0];
    const int*   ei    = (const int*)d_in[1];
    const int*   batch = (const int*)d_in[2];
    const float* W1m = (const float*)d_in[3];  const float* b1m = (const float*)d_in[4];
    const float* W2m = (const float*)d_in[5];  const float* b2m = (const float*)d_in[6];
    const float* W3m = (const float*)d_in[7];  const float* b3m = (const float*)d_in[8];
    const float* W1l = (const float*)d_in[9];  const float* b1l = (const float*)d_in[10];
    const float* W2l = (const float*)d_in[11]; const float* b2l = (const float*)d_in[12];
    const float* W3l = (const float*)d_in[13]; const float* b3l = (const float*)d_in[14];
    const float* Wfc = (const float*)d_in[15]; const float* bfc = (const float*)d_in[16];
    const float* eps = (const float*)d_in[17];
    float* out = (float*)d_out;

    const int* src = ei;
    const int* dst = ei + N_EDGES;

    const int NODE_BLKS = (N_NODES + 255) / 256;   // 391
    const int EDGE_BLKS = (N_EDGES + 255) / 256;   // 12500
    const int WARP_BLKS = N_NODES / 8;             // 12500 (exact)

    zeropack_kernel<<<NODE_BLKS, 256>>>(W1m, b1m, W2m, b2m, W3m, b3m,
                                        W1l, b1l, W2l, b2l, W3l, b3l);
    hist_count_kernel<<<EDGE_BLKS, 256>>>(dst, batch);
    scan1_kernel<<<NB_SCAN, 1024>>>();
    scan2_kernel<<<1, 128>>>();
    scan3_kernel<<<NB_SCAN, 1024>>>();
    fill_kernel<<<EDGE_BLKS, 256>>>(src, dst);

    dense1_kernel<<<WARP_BLKS, dim3(32, 8)>>>(x);

    // MEASUREMENT: gather1 and gather2 each launched twice. Both are pure
    // functions of untouched inputs (g_t1 / g_h1), so the duplicate recomputes
    // bit-identical outputs — correctness unchanged, and the dur_us delta vs
    // the 497us baseline is the true combined cost of gather1+gather2.
    gather1_kernel<<<WARP_BLKS, dim3(32, 8)>>>();
    gather1_kernel<<<WARP_BLKS, dim3(32, 8)>>>();
    gather2_dense_kernel<<<WARP_BLKS, dim3(32, 8)>>>();
    gather2_dense_kernel<<<WARP_BLKS, dim3(32, 8)>>>();
    gather3_dense_pool_kernel<<<WARP_BLKS, dim3(32, 8)>>>(batch);

    latent_kernel<<<16, 256>>>(eps, out);
    fc_kernel<<<FC_OUT / 256, dim3(64, 4)>>>(Wfc, bfc, out);
}

// round 15
// speedup vs baseline: 1.2743x; 1.2743x over previous
#include <cuda_runtime.h>
#include <cuda_bf16.h>
#include <math.h>

#define N_NODES   100000
#define N_EDGES   3200000
#define N_GRAPHS  64
#define FC_OUT    160000
#define NB_SCAN   98          // ceil(100000/1024)
#define FULLMASK  0xffffffffu

typedef __nv_bfloat16  bf16;
typedef __nv_bfloat162 bf162;

// ---------------- scratch (static __device__, no allocations) ----------------
__device__ int   g_deg[N_NODES];
__device__ float g_dinv[N_NODES];
__device__ int   g_rowptr[N_NODES + 1];
__device__ int   g_cursor[N_NODES];
__device__ int   g_blocksums[NB_SCAN + 1];
__device__ int   g_csr_src[N_EDGES];
__device__ bf16  g_t1[(size_t)N_NODES * 32];   // dinv-scaled x@W1
__device__ bf16  g_h1[(size_t)N_NODES * 32];   // dinv-scaled relu layer1
__device__ bf16  g_h2[(size_t)N_NODES * 64];   // dinv-scaled relu layer2
__device__ float g_W1f[64 * 32];
__device__ float g_b1f[32];
__device__ float g_W2f[32 * 64];
__device__ float g_b2f[64];
__device__ float g_W3f[64 * 128];
__device__ float g_b3f[128];
__device__ float g_pool[N_GRAPHS * 128];
__device__ int   g_cnt[N_GRAPHS];
__device__ float g_z[N_GRAPHS * 64];

// ---------------- init + weight packing (fused) ----------------
__global__ void zeropack_kernel(const float* __restrict__ W1m, const float* __restrict__ b1m,
                                const float* __restrict__ W2m, const float* __restrict__ b2m,
                                const float* __restrict__ W3m, const float* __restrict__ b3m,
                                const float* __restrict__ W1l, const float* __restrict__ b1l,
                                const float* __restrict__ W2l, const float* __restrict__ b2l,
                                const float* __restrict__ W3l, const float* __restrict__ b3l) {
    int i = blockIdx.x * 256 + threadIdx.x;
    if (i < N_NODES) g_deg[i] = 0;
    if (i < N_GRAPHS * 128) g_pool[i] = 0.f;
    if (i < N_GRAPHS) g_cnt[i] = 0;

    if (i < 64 * 32) {
        int j = i / 32, o = i % 32;
        g_W1f[i] = (o < 16) ? W1m[j * 16 + o] : W1l[j * 16 + (o - 16)];
    }
    if (i < 32) g_b1f[i] = (i < 16) ? b1m[i] : b1l[i - 16];
    if (i < 32 * 64) {
        int j = i / 64, o = i % 64;
        float v = 0.f;
        if (o < 32) { if (j < 16)  v = W2m[j * 32 + o]; }
        else        { if (j >= 16) v = W2l[(j - 16) * 32 + (o - 32)]; }
        g_W2f[i] = v;
    }
    if (i < 64) g_b2f[i] = (i < 32) ? b2m[i] : b2l[i - 32];
    if (i < 64 * 128) {
        int j = i / 128, o = i % 128;
        float v = 0.f;
        if (o < 64) { if (j < 32)  v = W3m[j * 64 + o]; }
        else        { if (j >= 32) v = W3l[(j - 32) * 64 + (o - 64)]; }
        g_W3f[i] = v;
    }
    if (i < 128) g_b3f[i] = (i < 64) ? b3m[i] : b3l[i - 64];
}

// ---------------- degree hist + per-graph node count (fused) ----------------
__global__ void hist_count_kernel(const int* __restrict__ dst, const int* __restrict__ batch) {
    int e = blockIdx.x * 256 + threadIdx.x;
    if (e < N_EDGES) atomicAdd(&g_deg[dst[e]], 1);
    if (e < N_NODES) atomicAdd(&g_cnt[batch[e]], 1);
}

// ---------------- scan (block-local) + dinv (fused) ----------------
__global__ void scan1_kernel() {
    __shared__ int sh[1024];
    int i = blockIdx.x * 1024 + threadIdx.x;
    int v = (i < N_NODES) ? g_deg[i] : 0;
    if (i < N_NODES) g_dinv[i] = rsqrtf((float)v + 1.0f);
    sh[threadIdx.x] = v;
    __syncthreads();
    for (int off = 1; off < 1024; off <<= 1) {
        int t = (threadIdx.x >= off) ? sh[threadIdx.x - off] : 0;
        __syncthreads();
        sh[threadIdx.x] += t;
        __syncthreads();
    }
    if (i < N_NODES) g_rowptr[i] = sh[threadIdx.x] - v;
    if (threadIdx.x == 1023) g_blocksums[blockIdx.x] = sh[1023];
}

// scan3 with integrated global prefix: each block sums blocksums[0..blockIdx)
__global__ void scan3_kernel() {
    __shared__ int ssum[128];
    int t = threadIdx.x;
    if (t < 128) ssum[t] = (t < blockIdx.x) ? g_blocksums[t] : 0;   // blockIdx < 98
    __syncthreads();
    if (t < 32) {
        int v = ssum[t] + ssum[t + 32] + ssum[t + 64] + ssum[t + 96];
#pragma unroll
        for (int off = 16; off > 0; off >>= 1)
            v += __shfl_xor_sync(FULLMASK, v, off);
        if (t == 0) ssum[0] = v;
    }
    __syncthreads();
    int off = ssum[0];
    int i = blockIdx.x * 1024 + t;
    if (i < N_NODES) {
        int r = g_rowptr[i] + off;
        g_rowptr[i] = r;
        g_cursor[i] = r;
    }
    if (i == 0) g_rowptr[N_NODES] = N_EDGES;
}

__global__ void fill_kernel(const int* __restrict__ src, const int* __restrict__ dst) {
    int e = blockIdx.x * 256 + threadIdx.x;
    if (e < N_EDGES) {
        int p = atomicAdd(&g_cursor[dst[e]], 1);
        g_csr_src[p] = src[e];
    }
}

// ---------------- pair-edge gather over 32-feature bf16 table (R6-proven) ----------
__device__ __forceinline__ float2 gather_pair32(const bf16* __restrict__ t, int i, int lane) {
    const int half = lane >> 4;
    const int l16 = lane & 15;
    int beg = __ldg(&g_rowptr[i]), end = __ldg(&g_rowptr[i + 1]);
    float ax = 0.f, ay = 0.f;
    int e = beg;
    while (e < end) {
        int cnt = min(end - e, 32);
        int idx = 0;
        if (lane < cnt) idx = __ldg(&g_csr_src[e + lane]);
        int pairs = cnt >> 1;
#pragma unroll 4
        for (int k = 0; k < pairs; k++) {
            int s = __shfl_sync(FULLMASK, idx, 2 * k + half);
            float2 f = __bfloat1622float2(__ldg((const bf162*)(t + (size_t)s * 32) + l16));
            ax += f.x; ay += f.y;
        }
        if (cnt & 1) {
            int s = __shfl_sync(FULLMASK, idx, cnt - 1);
            if (half == 0) {
                float2 f = __bfloat1622float2(__ldg((const bf162*)(t + (size_t)s * 32) + l16));
                ax += f.x; ay += f.y;
            }
        }
        e += cnt;
    }
    ax += __shfl_xor_sync(FULLMASK, ax, 16);
    ay += __shfl_xor_sync(FULLMASK, ay, 16);
    float2 fs = __bfloat1622float2(__ldg((const bf162*)(t + (size_t)i * 32) + l16));
    return make_float2(ax + fs.x, ay + fs.y);
}

// ---------------- pair-edge gather over 64-feature bf16 table (R6-proven) ----------
__device__ __forceinline__ float4 gather_pair64(const bf16* __restrict__ t, int i, int lane) {
    const int half = lane >> 4;
    const int l16 = lane & 15;
    int beg = __ldg(&g_rowptr[i]), end = __ldg(&g_rowptr[i + 1]);
    float a0 = 0.f, a1 = 0.f, a2 = 0.f, a3 = 0.f;
    int e = beg;
    while (e < end) {
        int cnt = min(end - e, 32);
        int idx = 0;
        if (lane < cnt) idx = __ldg(&g_csr_src[e + lane]);
        int pairs = cnt >> 1;
#pragma unroll 4
        for (int k = 0; k < pairs; k++) {
            int s = __shfl_sync(FULLMASK, idx, 2 * k + half);
            uint2 u = __ldg((const uint2*)(t + (size_t)s * 64) + l16);
            float2 f0 = __bfloat1622float2(*(const bf162*)&u.x);
            float2 f1 = __bfloat1622float2(*(const bf162*)&u.y);
            a0 += f0.x; a1 += f0.y; a2 += f1.x; a3 += f1.y;
        }
        if (cnt & 1) {
            int s = __shfl_sync(FULLMASK, idx, cnt - 1);
            if (half == 0) {
                uint2 u = __ldg((const uint2*)(t + (size_t)s * 64) + l16);
                float2 f0 = __bfloat1622float2(*(const bf162*)&u.x);
                float2 f1 = __bfloat1622float2(*(const bf162*)&u.y);
                a0 += f0.x; a1 += f0.y; a2 += f1.x; a3 += f1.y;
            }
        }
        e += cnt;
    }
    a0 += __shfl_xor_sync(FULLMASK, a0, 16);
    a1 += __shfl_xor_sync(FULLMASK, a1, 16);
    a2 += __shfl_xor_sync(FULLMASK, a2, 16);
    a3 += __shfl_xor_sync(FULLMASK, a3, 16);
    uint2 us = __ldg((const uint2*)(t + (size_t)i * 64) + l16);
    float2 s0 = __bfloat1622float2(*(const bf162*)&us.x);
    float2 s1 = __bfloat1622float2(*(const bf162*)&us.y);
    return make_float4(a0 + s0.x, a1 + s0.y, a2 + s1.x, a3 + s1.y);
}

// ---------------- dense1: t1' = dinv[i] * (x[i] @ W1f); warp does 4 nodes ----------
__global__ void dense1_kernel(const float* __restrict__ x) {
    __shared__ float Ws[64 * 32];
    int tid = threadIdx.y * 32 + threadIdx.x;
    for (int idx = tid; idx < 64 * 32; idx += 256) Ws[idx] = g_W1f[idx];
    __syncthreads();

    int o = threadIdx.x;
#pragma unroll
    for (int r = 0; r < 4; r++) {
        int i = blockIdx.x * 32 + threadIdx.y * 4 + r;
        const float2* xr = (const float2*)(x + (size_t)i * 64);
        float2 xv = __ldg(&xr[o]);
        float acc = 0.f;
#pragma unroll
        for (int jj = 0; jj < 32; jj++) {
            float vx = __shfl_sync(FULLMASK, xv.x, jj);
            float vy = __shfl_sync(FULLMASK, xv.y, jj);
            acc = fmaf(vx, Ws[(2 * jj) * 32 + o], acc);
            acc = fmaf(vy, Ws[(2 * jj + 1) * 32 + o], acc);
        }
        float di = __ldg(&g_dinv[i]);
        g_t1[(size_t)i * 32 + o] = __float2bfloat16(di * acc);
    }
}

// ---------------- G1: h1' = dinv * relu(dinv*(sum t1') + b1) (no weights; unchanged) ----
__global__ void gather1_kernel() {
    int i = blockIdx.x * 8 + threadIdx.y;
    int lane = threadIdx.x;
    int l16 = lane & 15;
    float2 g = gather_pair32(g_t1, i, lane);
    float di = __ldg(&g_dinv[i]);
    float2 b = __ldg((const float2*)g_b1f + l16);
    float h0 = fmaxf(fmaf(di, g.x, b.x), 0.f) * di;
    float h1 = fmaxf(fmaf(di, g.y, b.y), 0.f) * di;
    if (lane < 16)
        ((bf162*)(g_h1 + (size_t)i * 32))[l16] = __float22bfloat162_rn(make_float2(h0, h1));
}

// ---------------- G2+dense2: warp does 4 nodes (weights staged once per 32 nodes) ------
__global__ void gather2_dense_kernel() {
    __shared__ float Ws[32 * 64];
    int tid = threadIdx.y * 32 + threadIdx.x;
    for (int idx = tid; idx < 32 * 64; idx += 256) Ws[idx] = g_W2f[idx];
    __syncthreads();

    int l = threadIdx.x;
#pragma unroll
    for (int r = 0; r < 4; r++) {
        int i = blockIdx.x * 32 + threadIdx.y * 4 + r;
        float2 gp = gather_pair32(g_h1, i, l);   // lane: g2[2*(l&15)], g2[2*(l&15)+1]
        float di = __ldg(&g_dinv[i]);
        float g2x = di * gp.x, g2y = di * gp.y;

        // block-diagonal dense: out[l] from j 0..15 (mu), out[l+32] from j 16..31 (logvar)
        float accA = __ldg(&g_b2f[l]);
        float accB = __ldg(&g_b2f[l + 32]);
#pragma unroll
        for (int jj = 0; jj < 8; jj++) {
            float vx = __shfl_sync(FULLMASK, g2x, jj);        // feature 2jj
            float vy = __shfl_sync(FULLMASK, g2y, jj);        // feature 2jj+1
            accA = fmaf(vx, Ws[(2 * jj) * 64 + l], accA);
            accA = fmaf(vy, Ws[(2 * jj + 1) * 64 + l], accA);
        }
#pragma unroll
        for (int jj = 8; jj < 16; jj++) {
            float vx = __shfl_sync(FULLMASK, g2x, jj);        // feature 2jj (16..31)
            float vy = __shfl_sync(FULLMASK, g2y, jj);
            accB = fmaf(vx, Ws[(2 * jj) * 64 + 32 + l], accB);
            accB = fmaf(vy, Ws[(2 * jj + 1) * 64 + 32 + l], accB);
        }
        float h2a = fmaxf(accA, 0.f), h2b = fmaxf(accB, 0.f);
        g_h2[(size_t)i * 64 + l]      = __float2bfloat16(di * h2a);
        g_h2[(size_t)i * 64 + l + 32] = __float2bfloat16(di * h2b);
    }
}

// ---------------- G3+dense3+pool: warp does 4 nodes (32KB weights per 32 nodes) --------
__global__ void gather3_dense_pool_kernel(const int* __restrict__ batch) {
    __shared__ float Ws[64 * 128];     // 32 KB
    __shared__ float pacc[128];
    int tid = threadIdx.y * 32 + threadIdx.x;
    for (int idx = tid; idx < 64 * 128; idx += 256) Ws[idx] = g_W3f[idx];
    if (tid < 128) pacc[tid] = 0.f;
    __syncthreads();

    int l = threadIdx.x;
    int g0 = __ldg(&batch[blockIdx.x * 32]);

#pragma unroll
    for (int r = 0; r < 4; r++) {
        int i = blockIdx.x * 32 + threadIdx.y * 4 + r;
        float4 gp = gather_pair64(g_h2, i, l);   // lane: g3[4*(l&15) .. +3]
        float di = __ldg(&g_dinv[i]);
        float v0 = di * gp.x, v1 = di * gp.y, v2 = di * gp.z, v3 = di * gp.w;

        float a0 = __ldg(&g_b3f[2 * l]);
        float a1 = __ldg(&g_b3f[2 * l + 1]);
        float a2 = __ldg(&g_b3f[64 + 2 * l]);
        float a3 = __ldg(&g_b3f[65 + 2 * l]);
#pragma unroll
        for (int jj = 0; jj < 8; jj++) {   // features 4jj..4jj+3 (0..31)
            float w0 = __shfl_sync(FULLMASK, v0, jj);
            float w1 = __shfl_sync(FULLMASK, v1, jj);
            float w2 = __shfl_sync(FULLMASK, v2, jj);
            float w3 = __shfl_sync(FULLMASK, v3, jj);
            a0 = fmaf(w0, Ws[(4 * jj) * 128 + 2 * l], a0);
            a0 = fmaf(w1, Ws[(4 * jj + 1) * 128 + 2 * l], a0);
            a0 = fmaf(w2, Ws[(4 * jj + 2) * 128 + 2 * l], a0);
            a0 = fmaf(w3, Ws[(4 * jj + 3) * 128 + 2 * l], a0);
            a1 = fmaf(w0, Ws[(4 * jj) * 128 + 2 * l + 1], a1);
            a1 = fmaf(w1, Ws[(4 * jj + 1) * 128 + 2 * l + 1], a1);
            a1 = fmaf(w2, Ws[(4 * jj + 2) * 128 + 2 * l + 1], a1);
            a1 = fmaf(w3, Ws[(4 * jj + 3) * 128 + 2 * l + 1], a1);
        }
#pragma unroll
        for (int jj = 8; jj < 16; jj++) {  // features 4jj..4jj+3 (32..63)
            float w0 = __shfl_sync(FULLMASK, v0, jj);
            float w1 = __shfl_sync(FULLMASK, v1, jj);
            float w2 = __shfl_sync(FULLMASK, v2, jj);
            float w3 = __shfl_sync(FULLMASK, v3, jj);
            a2 = fmaf(w0, Ws[(4 * jj) * 128 + 64 + 2 * l], a2);
            a2 = fmaf(w1, Ws[(4 * jj + 1) * 128 + 64 + 2 * l], a2);
            a2 = fmaf(w2, Ws[(4 * jj + 2) * 128 + 64 + 2 * l], a2);
            a2 = fmaf(w3, Ws[(4 * jj + 3) * 128 + 64 + 2 * l], a2);
            a3 = fmaf(w0, Ws[(4 * jj) * 128 + 65 + 2 * l], a3);
            a3 = fmaf(w1, Ws[(4 * jj + 1) * 128 + 65 + 2 * l], a3);
            a3 = fmaf(w2, Ws[(4 * jj + 2) * 128 + 65 + 2 * l], a3);
            a3 = fmaf(w3, Ws[(4 * jj + 3) * 128 + 65 + 2 * l], a3);
        }
        a0 = fmaxf(a0, 0.f); a1 = fmaxf(a1, 0.f);
        a2 = fmaxf(a2, 0.f); a3 = fmaxf(a3, 0.f);

        int g = __ldg(&batch[i]);
        if (g == g0) {
            atomicAdd(&pacc[2 * l], a0);
            atomicAdd(&pacc[2 * l + 1], a1);
            atomicAdd(&pacc[64 + 2 * l], a2);
            atomicAdd(&pacc[65 + 2 * l], a3);
        } else {   // rare graph-boundary nodes
            atomicAdd(&g_pool[g * 128 + 2 * l], a0);
            atomicAdd(&g_pool[g * 128 + 2 * l + 1], a1);
            atomicAdd(&g_pool[g * 128 + 64 + 2 * l], a2);
            atomicAdd(&g_pool[g * 128 + 65 + 2 * l], a3);
        }
    }
    __syncthreads();
    if (tid < 128) atomicAdd(&g_pool[g0 * 128 + tid], pacc[tid]);
}

// ---------------- latent: mu, logvar, z ----------------
__global__ void latent_kernel(const float* __restrict__ eps, float* __restrict__ d_out) {
    int idx = blockIdx.x * 256 + threadIdx.x;
    if (idx >= N_GRAPHS * 64) return;
    int g = idx >> 6, f = idx & 63;
    float c = fmaxf((float)g_cnt[g], 1.0f);
    float mu = g_pool[g * 128 + f] / c;
    float lv = g_pool[g * 128 + 64 + f] / c;
    d_out[(size_t)N_GRAPHS * FC_OUT + idx] = mu;
    d_out[(size_t)N_GRAPHS * FC_OUT + N_GRAPHS * 64 + idx] = lv;
    g_z[idx] = mu + eps[idx] * expf(0.5f * lv);
}

// ---------------- FC decode: sigmoid(z @ Wfc + bfc) ----------------
__global__ void fc_kernel(const float* __restrict__ Wfc,
                          const float* __restrict__ bfc,
                          float* __restrict__ out) {
    __shared__ float zT[64 * 65];
    int tid = threadIdx.y * 64 + threadIdx.x;
    for (int i = tid; i < 64 * 64; i += 256) {
        int g = i & 63, j = i >> 6;
        zT[j * 65 + g] = g_z[g * 64 + j];
    }
    __syncthreads();

    int kq = blockIdx.x * 64 + threadIdx.x;
    int g0 = threadIdx.y * 16;
    const float4* W4 = (const float4*)Wfc;
    float4 bv = ((const float4*)bfc)[kq];

    float4 acc[16];
#pragma unroll
    for (int gi = 0; gi < 16; gi++) acc[gi] = bv;

#pragma unroll 4
    for (int j = 0; j < 64; j++) {
        float4 w = W4[(size_t)j * (FC_OUT / 4) + kq];
#pragma unroll
        for (int gi = 0; gi < 16; gi++) {
            float zv = zT[j * 65 + g0 + gi];
            acc[gi].x = fmaf(zv, w.x, acc[gi].x);
            acc[gi].y = fmaf(zv, w.y, acc[gi].y);
            acc[gi].z = fmaf(zv, w.z, acc[gi].z);
            acc[gi].w = fmaf(zv, w.w, acc[gi].w);
        }
    }

#pragma unroll
    for (int gi = 0; gi < 16; gi++) {
        int g = g0 + gi;
        float4 v = acc[gi];
        v.x = 1.f / (1.f + __expf(-v.x));
        v.y = 1.f / (1.f + __expf(-v.y));
        v.z = 1.f / (1.f + __expf(-v.z));
        v.w = 1.f / (1.f + __expf(-v.w));
        ((float4*)out)[(size_t)g * (FC_OUT / 4) + kq] = v;
    }
}

// ---------------- launch ----------------
extern "C" void kernel_launch(void* const* d_in, const int* in_sizes, int n_in,
                              void* d_out, int out_size) {
    const float* x     = (const float*)d_in[0];
    const int*   ei    = (const int*)d_in[1];
    const int*   batch = (const int*)d_in[2];
    const float* W1m = (const float*)d_in[3];  const float* b1m = (const float*)d_in[4];
    const float* W2m = (const float*)d_in[5];  const float* b2m = (const float*)d_in[6];
    const float* W3m = (const float*)d_in[7];  const float* b3m = (const float*)d_in[8];
    const float* W1l = (const float*)d_in[9];  const float* b1l = (const float*)d_in[10];
    const float* W2l = (const float*)d_in[11]; const float* b2l = (const float*)d_in[12];
    const float* W3l = (const float*)d_in[13]; const float* b3l = (const float*)d_in[14];
    const float* Wfc = (const float*)d_in[15]; const float* bfc = (const float*)d_in[16];
    const float* eps = (const float*)d_in[17];
    float* out = (float*)d_out;

    const int* src = ei;
    const int* dst = ei + N_EDGES;

    const int NODE_BLKS = (N_NODES + 255) / 256;   // 391
    const int EDGE_BLKS = (N_EDGES + 255) / 256;   // 12500
    const int WARP_BLKS = N_NODES / 8;             // 12500 (exact)
    const int QUAD_BLKS = N_NODES / 32;            // 3125  (exact)

    zeropack_kernel<<<NODE_BLKS, 256>>>(W1m, b1m, W2m, b2m, W3m, b3m,
                                        W1l, b1l, W2l, b2l, W3l, b3l);
    hist_count_kernel<<<EDGE_BLKS, 256>>>(dst, batch);
    scan1_kernel<<<NB_SCAN, 1024>>>();
    scan3_kernel<<<NB_SCAN, 1024>>>();
    fill_kernel<<<EDGE_BLKS, 256>>>(src, dst);

    dense1_kernel<<<QUAD_BLKS, dim3(32, 8)>>>(x);
    gather1_kernel<<<WARP_BLKS, dim3(32, 8)>>>();
    gather2_dense_kernel<<<QUAD_BLKS, dim3(32, 8)>>>();
    gather3_dense_pool_kernel<<<QUAD_BLKS, dim3(32, 8)>>>(batch);

    latent_kernel<<<16, 256>>>(eps, out);
    fc_kernel<<<FC_OUT / 256, dim3(64, 4)>>>(Wfc, bfc, out);
}